// round 1
// baseline (speedup 1.0000x reference)
#include <cuda_runtime.h>
#include <math.h>

// Problem shape (fixed by the dataset)
#define TT 2048
#define BB 64
#define KIN 256
#define HH 256

// Scratch for the precomputed input projection xp[t][b][h]  (134 MB, static
// device global -- the sanctioned alloc-free scratch mechanism).
__device__ float g_xp[(size_t)TT * BB * HH];

// ---------------------------------------------------------------------------
// Kernel 1: xp[m][n] = sum_k x[m][k] * W_ih[n][k] + b_ih[n] + b_hh[n]
//   m = t*B + b  (row-major [T,B,IN] flattens to [M=131072, K=256])
//   Register-tiled 128x128 block, BK=16, 256 threads, 8x8 per-thread tile.
// ---------------------------------------------------------------------------
__global__ __launch_bounds__(256, 2) void xp_gemm_kernel(
    const float* __restrict__ x,
    const float* __restrict__ Wih,
    const float* __restrict__ b_ih,
    const float* __restrict__ b_hh)
{
    __shared__ float As[16][132];   // [k][m] transposed, padded
    __shared__ float Bs[16][132];   // [k][n] transposed, padded

    const int tid = threadIdx.x;
    const int m0 = blockIdx.x * 128;
    const int n0 = blockIdx.y * 128;
    const int ty = tid >> 4;        // 0..15 -> m direction
    const int tx = tid & 15;        // 0..15 -> n direction

    float acc[8][8];
#pragma unroll
    for (int i = 0; i < 8; i++)
#pragma unroll
        for (int j = 0; j < 8; j++) acc[i][j] = 0.0f;

    for (int kt = 0; kt < KIN; kt += 16) {
        // Cooperative load of A(128x16) and B(128x16), transposed into smem.
#pragma unroll
        for (int l = 0; l < 2; l++) {
            int id  = tid + l * 256;      // 0..511
            int row = id >> 2;            // 0..127
            int c4  = (id & 3) * 4;       // 0,4,8,12
            float4 av = *(const float4*)(x   + (size_t)(m0 + row) * KIN + kt + c4);
            As[c4 + 0][row] = av.x; As[c4 + 1][row] = av.y;
            As[c4 + 2][row] = av.z; As[c4 + 3][row] = av.w;
            float4 bv = *(const float4*)(Wih + (size_t)(n0 + row) * KIN + kt + c4);
            Bs[c4 + 0][row] = bv.x; Bs[c4 + 1][row] = bv.y;
            Bs[c4 + 2][row] = bv.z; Bs[c4 + 3][row] = bv.w;
        }
        __syncthreads();

#pragma unroll
        for (int k = 0; k < 16; k++) {
            float a[8], b[8];
#pragma unroll
            for (int i = 0; i < 8; i++) a[i] = As[k][ty * 8 + i];
#pragma unroll
            for (int j = 0; j < 8; j++) b[j] = Bs[k][tx * 8 + j];
#pragma unroll
            for (int i = 0; i < 8; i++)
#pragma unroll
                for (int j = 0; j < 8; j++)
                    acc[i][j] = fmaf(a[i], b[j], acc[i][j]);
        }
        __syncthreads();
    }

    // Epilogue: add fused bias, store.
    float bb[8];
#pragma unroll
    for (int j = 0; j < 8; j++) {
        int n = n0 + tx * 8 + j;
        bb[j] = b_ih[n] + b_hh[n];
    }
#pragma unroll
    for (int i = 0; i < 8; i++) {
        float* dst = g_xp + (size_t)(m0 + ty * 8 + i) * HH + n0 + tx * 8;
        float4 v0 = make_float4(acc[i][0] + bb[0], acc[i][1] + bb[1],
                                acc[i][2] + bb[2], acc[i][3] + bb[3]);
        float4 v1 = make_float4(acc[i][4] + bb[4], acc[i][5] + bb[5],
                                acc[i][6] + bb[6], acc[i][7] + bb[7]);
        *(float4*)dst       = v0;
        *(float4*)(dst + 4) = v1;
    }
}

// ---------------------------------------------------------------------------
// Kernel 2: serial recurrence. One CTA per batch element (64 CTAs), 512 thr.
//   Thread t: j = t & 255 (output row), half = t >> 8 (K-split).
//   W_hh[j][k0 .. k0+91]   -> 92 registers per thread (register-resident W)
//   W_hh[j][k0+92..k0+127] -> 36 floats in SMEM (9 float4, conflict-free)
//   Per step: 128-FMA partial dot, pair-reduce via smem, tanh, broadcast h.
// ---------------------------------------------------------------------------
__global__ __launch_bounds__(512, 1) void rnn_scan_kernel(
    const float* __restrict__ Whh,
    float* __restrict__ out)
{
    extern __shared__ float smem[];
    // layout: Wsm (9*512 float4 = 18432 floats) | hsm(256) | red(256)
    float4* Wsm4 = (float4*)smem;
    float*  hsm  = smem + 9 * 512 * 4;
    float*  red  = hsm + 256;

    const int tid  = threadIdx.x;
    const int b    = blockIdx.x;
    const int j    = tid & 255;
    const int half = tid >> 8;
    const int k0   = half * 128;

    // Stage W: 92 regs + 36 smem floats per thread.
    float wr[92];
    const float* wrow = Whh + (size_t)j * HH + k0;
#pragma unroll
    for (int i = 0; i < 92; i++) wr[i] = wrow[i];
    const float4* wsrc = (const float4*)(wrow + 92);   // 92*4 = 368 B, 16B aligned
#pragma unroll
    for (int g = 0; g < 9; g++) Wsm4[g * 512 + tid] = wsrc[g];

    if (tid < 256) hsm[tid] = 0.0f;     // h0 = 0
    __syncthreads();

    const float* xpb  = g_xp + (size_t)b * HH;
    float*       outb = out  + (size_t)b * HH;
    const size_t tstride = (size_t)BB * HH;

    for (int t = 0; t < TT; t++) {
        // Prefetch this step's xp (only the half==1 threads consume it).
        float xv = 0.0f;
        if (half) xv = xpb[(size_t)t * tstride + j];

        const float4* h4 = (const float4*)(hsm + k0);
        float acc0 = 0.0f, acc1 = 0.0f;
#pragma unroll
        for (int g = 0; g < 23; g++) {
            float4 hv = h4[g];
            acc0 = fmaf(wr[4 * g + 0], hv.x, acc0);
            acc1 = fmaf(wr[4 * g + 1], hv.y, acc1);
            acc0 = fmaf(wr[4 * g + 2], hv.z, acc0);
            acc1 = fmaf(wr[4 * g + 3], hv.w, acc1);
        }
#pragma unroll
        for (int g = 0; g < 9; g++) {
            float4 wv = Wsm4[g * 512 + tid];
            float4 hv = h4[23 + g];
            acc0 = fmaf(wv.x, hv.x, acc0);
            acc1 = fmaf(wv.y, hv.y, acc1);
            acc0 = fmaf(wv.z, hv.z, acc0);
            acc1 = fmaf(wv.w, hv.w, acc1);
        }
        float acc = acc0 + acc1;

        if (!half) red[j] = acc;
        __syncthreads();                 // red visible; all hsm reads done
        if (half) {
            float hn = tanhf(acc + red[j] + xv);
            hsm[j] = hn;
            outb[(size_t)t * tstride + j] = hn;
        }
        __syncthreads();                 // hsm update visible for next step
    }
}

// ---------------------------------------------------------------------------
// Launch
// ---------------------------------------------------------------------------
extern "C" void kernel_launch(void* const* d_in, const int* in_sizes, int n_in,
                              void* d_out, int out_size)
{
    const float* x    = (const float*)d_in[0];
    const float* Wih  = (const float*)d_in[1];
    const float* Whh  = (const float*)d_in[2];
    const float* b_ih = (const float*)d_in[3];
    const float* b_hh = (const float*)d_in[4];
    float* out = (float*)d_out;

    // Kernel 1: input projection for all timesteps.
    dim3 g1((TT * BB) / 128, HH / 128);
    xp_gemm_kernel<<<g1, 256>>>(x, Wih, b_ih, b_hh);

    // Kernel 2: serial scan, one CTA per batch element.
    const int smem_bytes = (9 * 512 * 4 + 256 + 256) * (int)sizeof(float); // 75776
    cudaFuncSetAttribute(rnn_scan_kernel,
                         cudaFuncAttributeMaxDynamicSharedMemorySize, smem_bytes);
    rnn_scan_kernel<<<BB, 512, smem_bytes>>>(Whh, out);
}